// round 10
// baseline (speedup 1.0000x reference)
#include <cuda_runtime.h>
#include <cuda_bf16.h>
#include <cstdint>

// GridSample bilinear, zeros padding, align_corners=True.
// x: [8, 64, 256, 256] fp32 ; grid: [8, 256, 256, 2] fp32 (dx,dy pixel offsets)
// out: [8, 64, 256, 256] fp32
//
// SMEM-staged gather, QUAD-buffered cp.async pipeline (wait_group 2 -> ~3
// iterations of latency cover), one barrier per channel, 512-thread blocks
// (8-row band x 16 channels), two CTAs co-resident per SM.

#define GS_N 8
#define GS_C 64
#define GS_H 256
#define GS_W 256
#define GS_PLANE (GS_H * GS_W)          // 65536
#define TILE_H 8
#define HALO 8
#define STAGE_H (TILE_H + 2 * HALO)      // 24 staged rows
#define STAGE_F4 (STAGE_H * (GS_W / 4))  // 1536 float4 per buffer
#define NBUF 4
#define CH_GRP 16
#define THREADS 512
#define POS_PER_THR 4                    // 8*256/512
#define SLOTS 3                          // 1536/512 stage float4s per thread
#define SMEM_BYTES (NBUF * STAGE_H * GS_W * 4)   // 98304

__device__ __forceinline__ void cp_async16(uint32_t smem_addr, const void* gptr) {
    asm volatile("cp.async.cg.shared.global [%0], [%1], 16;\n"
                 :: "r"(smem_addr), "l"(gptr));
}
__device__ __forceinline__ void cp_commit() {
    asm volatile("cp.async.commit_group;\n");
}
template <int N>
__device__ __forceinline__ void cp_wait() {
    asm volatile("cp.async.wait_group %0;\n" :: "n"(N));
}

__global__ void __launch_bounds__(THREADS, 2) gridsample_kernel(
    const float* __restrict__ x,
    const float* __restrict__ grid,
    float* __restrict__ out)
{
    extern __shared__ float tile[];   // NBUF x 6144 floats

    const int b  = blockIdx.x;               // 1024 blocks
    const int cg = b & 3;                    // channel group (16 ch)
    const int th = (b >> 2) & 31;            // row-band tile (8 rows)
    const int n  = b >> 7;                   // batch
    const int row_base = th * TILE_H;
    const int chbase   = n * GS_C + cg * CH_GRP;
    const int tid = threadIdx.x;

    const float4* __restrict__ x4 = reinterpret_cast<const float4*>(x);
    const uint32_t smem_base =
        static_cast<uint32_t>(__cvta_generic_to_shared(tile));

    // Per-thread staged float4 slots (clamped-row global offsets in a plane).
    int goff[SLOTS];
    #pragma unroll
    for (int k = 0; k < SLOTS; ++k) {
        const int i  = tid + k * THREADS;
        const int r  = i >> 6;                // 64 float4 per row
        const int c4 = i & 63;
        const int gy = min(max(row_base - HALO + r, 0), GS_H - 1);
        goff[k] = gy * (GS_W / 4) + c4;
    }

    // ---- Prologue: stage ch0..ch2 -> buf0..buf2 ----
    #pragma unroll
    for (int c = 0; c < NBUF - 1; ++c) {
        const int plane = chbase + c;
        const uint32_t dst = smem_base + (uint32_t)c * (STAGE_F4 * 16u);
        #pragma unroll
        for (int k = 0; k < SLOTS; ++k) {
            const int i = tid + k * THREADS;
            cp_async16(dst + (uint32_t)i * 16u,
                       x4 + plane * (GS_PLANE / 4) + goff[k]);
        }
        cp_commit();
    }

    // ---- Weights + packed corner coords for this thread's 4 positions ----
    const int spatial_base = n * GS_PLANE + row_base * GS_W;
    float w00[POS_PER_THR], w01[POS_PER_THR], w10[POS_PER_THR], w11[POS_PER_THR];
    int   pk[POS_PER_THR];   // (s0<<26)|(s1<<20)|(cx0<<8)|cx1

    #pragma unroll
    for (int k = 0; k < POS_PER_THR; ++k) {
        const int p  = tid + k * THREADS;    // 0..2047 within the band
        const int wo = p & (GS_W - 1);
        const int ho = row_base + (p >> 8);

        const float2 g = __ldg(reinterpret_cast<const float2*>(grid) +
                               (spatial_base + p));

        const float abs_x = g.x + (float)wo;
        const float abs_y = g.y + (float)ho;
        const float norm_x = abs_x * 2.0f / (float)(GS_W - 1) - 1.0f;
        const float norm_y = abs_y * 2.0f / (float)(GS_H - 1) - 1.0f;
        const float ix = (norm_x + 1.0f) * 0.5f * (float)(GS_W - 1);
        const float iy = (norm_y + 1.0f) * 0.5f * (float)(GS_H - 1);

        const float x0f = floorf(ix);
        const float y0f = floorf(iy);
        const float wx1 = ix - x0f, wx0 = 1.0f - wx1;
        const float wy1 = iy - y0f, wy0 = 1.0f - wy1;

        const int x0 = (int)x0f, x1 = x0 + 1;
        const int y0 = (int)y0f, y1 = y0 + 1;

        const bool bx0 = (x0 >= 0) & (x0 <= GS_W - 1);
        const bool bx1 = (x1 >= 0) & (x1 <= GS_W - 1);
        const bool by0 = (y0 >= 0) & (y0 <= GS_H - 1);
        const bool by1 = (y1 >= 0) & (y1 <= GS_H - 1);

        w00[k] = wy0 * wx0 * (float)(by0 & bx0);
        w01[k] = wy0 * wx1 * (float)(by0 & bx1);
        w10[k] = wy1 * wx0 * (float)(by1 & bx0);
        w11[k] = wy1 * wx1 * (float)(by1 & bx1);

        const int cx0 = min(max(x0, 0), GS_W - 1);
        const int cx1 = min(max(x1, 0), GS_W - 1);
        const int cy0 = min(max(y0, 0), GS_H - 1);
        const int cy1 = min(max(y1, 0), GS_H - 1);

        const int s0 = min(max(cy0 - row_base + HALO, 0), STAGE_H - 1);
        const int s1 = min(max(cy1 - row_base + HALO, 0), STAGE_H - 1);

        pk[k] = (s0 << 26) | (s1 << 20) | (cx0 << 8) | cx1;
    }

    // ---- Channel loop: 1 barrier per channel, depth-4 buffers ----
    for (int ch = 0; ch < CH_GRP; ++ch) {
        // Group for ch must be done; up to min(2, CH_GRP-1-ch) newer in flight.
        if (ch <= CH_GRP - 3)      cp_wait<2>();
        else if (ch == CH_GRP - 2) cp_wait<1>();
        else                       cp_wait<0>();

        // Single barrier: ch's stage visible to all + WAR guard for
        // re-staging buffer (ch+3)%4 == (ch-1)%4 (its gathers finished
        // before this barrier).
        __syncthreads();

        if (ch + NBUF - 1 < CH_GRP) {
            const int plane = chbase + ch + NBUF - 1;
            const uint32_t dst = smem_base +
                (uint32_t)((ch + NBUF - 1) % NBUF) * (STAGE_F4 * 16u);
            #pragma unroll
            for (int k = 0; k < SLOTS; ++k) {
                const int i = tid + k * THREADS;
                cp_async16(dst + (uint32_t)i * 16u,
                           x4 + plane * (GS_PLANE / 4) + goff[k]);
            }
            cp_commit();
        }

        const float* buf = tile + (ch % NBUF) * (STAGE_F4 * 4);
        const int plane = chbase + ch;
        const int obase = plane * GS_PLANE + row_base * GS_W;

        #pragma unroll
        for (int k = 0; k < POS_PER_THR; ++k) {
            const int pkk = pk[k];
            const int r0  = (pkk >> 26) << 8;          // s0 * 256
            const int r1  = ((pkk >> 20) & 63) << 8;   // s1 * 256
            const int cx0 = (pkk >> 8) & 255;
            const int cx1 = pkk & 255;
            const float v = buf[r0 + cx0] * w00[k] + buf[r0 + cx1] * w01[k]
                          + buf[r1 + cx0] * w10[k] + buf[r1 + cx1] * w11[k];
            __stcs(&out[obase + tid + k * THREADS], v);   // streaming store
        }
    }
}

extern "C" void kernel_launch(void* const* d_in, const int* in_sizes, int n_in,
                              void* d_out, int out_size)
{
    const float* x    = (const float*)d_in[0];
    const float* grid = (const float*)d_in[1];
    float* out        = (float*)d_out;

    cudaFuncSetAttribute(gridsample_kernel,
                         cudaFuncAttributeMaxDynamicSharedMemorySize,
                         SMEM_BYTES);

    const int blocks = GS_N * (GS_H / TILE_H) * (GS_C / CH_GRP);  // 1024
    gridsample_kernel<<<blocks, THREADS, SMEM_BYTES>>>(x, grid, out);
}